// round 8
// baseline (speedup 1.0000x reference)
#include <cuda_runtime.h>
#include <cuda_bf16.h>
#include <math.h>
#include <stdint.h>

#define Bz   128
#define Tz   1024
#define INz  256
#define Hz   512
#define G4   2048   // 4*H
#define NCTA 128

// ---------------- scratch (device globals) ---------------------------------
__device__ float g_xg[(size_t)Bz * Tz * G4];       // gate preacts, PERMUTED cols
__device__ __nv_bfloat16 g_hsb[(size_t)Bz * Tz * Hz]; // layer-0 hidden outputs, bf16 plain
__device__ unsigned g_phb[2][4][8192];             // h exchange, bf16 A-frag layout
__device__ float g_hlast[Bz * Hz];                 // final h of running layer
__device__ unsigned g_flag[4][32];                 // per-CTA progress flags (per bt group)

// ---------------------------------------------------------------------------
__device__ __forceinline__ void mma_bf16(float* d, const uint4& a, unsigned b0, unsigned b1) {
    asm volatile(
        "mma.sync.aligned.m16n8k16.row.col.f32.bf16.bf16.f32 "
        "{%0,%1,%2,%3}, {%4,%5,%6,%7}, {%8,%9}, {%0,%1,%2,%3};\n"
        : "+f"(d[0]), "+f"(d[1]), "+f"(d[2]), "+f"(d[3])
        : "r"(a.x), "r"(a.y), "r"(a.z), "r"(a.w), "r"(b0), "r"(b1));
}
__device__ __forceinline__ float tanha(float x) {
    float y; asm("tanh.approx.f32 %0, %1;" : "=f"(y) : "f"(x)); return y;
}
__device__ __forceinline__ float siga(float x) { return 0.5f * tanha(0.5f * x) + 0.5f; }
__device__ __forceinline__ unsigned pack_bf16x2(float x, float y) {
    __nv_bfloat162 v = __floats2bfloat162_rn(x, y);
    return *(unsigned*)&v;
}

// ---------------------------------------------------------------------------
__global__ void zero_state_kernel() {
    int i = blockIdx.x * blockDim.x + threadIdx.x;
    if (i < 2 * 4 * 8192) ((unsigned*)g_phb)[i] = 0u;
    else if (i < 2 * 4 * 8192 + 4 * 32) ((unsigned*)g_flag)[i - 2 * 4 * 8192] = 0u;
}

// ---------------------------------------------------------------------------
// Input GEMM, bf16 m16n8k16. BM=128, BN=64, BK=32, 256 thr (4m x 2n warps).
// Output to g_xg with permuted gate cols: n' = jj*4+gate, row = (n'&3)*Hz+(n'>>2)
// ---------------------------------------------------------------------------
template <int K, bool BF16IN>
__global__ void __launch_bounds__(256) gemm_bf16_kernel(
    const float* __restrict__ Xf, const float* __restrict__ W,
    const float* __restrict__ b1, const float* __restrict__ b2)
{
    __shared__ uint4 Abuf[8][2][32];   // [m16][k16 step][lane] 8KB
    __shared__ uint2 Bbuf[8][2][32];   // [n8][k16 step][lane]  2KB
    __shared__ float sbias[64];

    const __nv_bfloat16* __restrict__ Xb = g_hsb;

    int tid = threadIdx.x, lane = tid & 31, warp = tid >> 5;
    int wm = warp & 3, wn = warp >> 2;
    int g = lane >> 2, tig = lane & 3;
    size_t m0g = (size_t)blockIdx.y * 128;
    int    n0g = blockIdx.x * 64;

    if (tid < 64) {
        int ng  = n0g + tid;
        int row = (ng & 3) * Hz + (ng >> 2);
        sbias[tid] = b1[row] + b2[row];
    }

    float d[2][4][4];
#pragma unroll
    for (int a = 0; a < 2; a++)
#pragma unroll
        for (int b = 0; b < 4; b++)
#pragma unroll
            for (int c = 0; c < 4; c++) d[a][b][c] = 0.0f;

    for (int kb = 0; kb < K; kb += 32) {
        // ---- A fill: 4 quads/thread (quad = 4 consecutive k at one row) ----
#pragma unroll
        for (int i = 0; i < 4; i++) {
            int f4 = tid * 4 + i;            // 0..1023
            int m = f4 >> 3, q = f4 & 7;
            unsigned lo_, hi_;
            if (BF16IN) {
                uint2 u = *(const uint2*)&Xb[(m0g + m) * K + kb + q * 4];
                lo_ = u.x; hi_ = u.y;
            } else {
                float4 v = *(const float4*)&Xf[(m0g + m) * K + kb + q * 4];
                lo_ = pack_bf16x2(v.x, v.y); hi_ = pack_bf16x2(v.z, v.w);
            }
            int mt = m >> 4, gg = m & 7, odd = (m >> 3) & 1;
            int ks = q >> 2, kc = (q >> 1) & 1, tg2 = (q & 1) * 2;
            int e = odd + 2 * kc;
            ((unsigned*)&Abuf[mt][ks][gg * 4 + tg2])[e]     = lo_;
            ((unsigned*)&Abuf[mt][ks][gg * 4 + tg2 + 1])[e] = hi_;
        }
        // ---- B fill: 2 quads/thread ----
#pragma unroll
        for (int i = 0; i < 2; i++) {
            int fb = tid * 2 + i;            // 0..511
            int n = fb >> 3, q = fb & 7;
            int row = ((n0g + n) & 3) * Hz + ((n0g + n) >> 2);
            float4 v = *(const float4*)&W[(size_t)row * K + kb + q * 4];
            unsigned lo_ = pack_bf16x2(v.x, v.y), hi_ = pack_bf16x2(v.z, v.w);
            int nt = n >> 3, gb = n & 7;
            int ks = q >> 2, r = (q >> 1) & 1, tg = (q & 1) * 2;
            ((unsigned*)&Bbuf[nt][ks][gb * 4 + tg])[r]     = lo_;
            ((unsigned*)&Bbuf[nt][ks][gb * 4 + tg + 1])[r] = hi_;
        }
        __syncthreads();
#pragma unroll
        for (int ks = 0; ks < 2; ks++) {
            uint4 a0 = Abuf[wm * 2 + 0][ks][lane];
            uint4 a1 = Abuf[wm * 2 + 1][ks][lane];
#pragma unroll
            for (int j = 0; j < 4; j++) {
                uint2 bb = Bbuf[wn * 4 + j][ks][lane];
                mma_bf16(d[0][j], a0, bb.x, bb.y);
                mma_bf16(d[1][j], a1, bb.x, bb.y);
            }
        }
        __syncthreads();
    }

    // ---- epilogue: add bias, store permuted (fp32) ----
#pragma unroll
    for (int mt = 0; mt < 2; mt++) {
#pragma unroll
        for (int j = 0; j < 4; j++) {
            int col = wn * 32 + j * 8 + 2 * tig;
            float bi0 = sbias[col], bi1 = sbias[col + 1];
            size_t m = m0g + wm * 32 + mt * 16 + g;
            float2 v0 = make_float2(d[mt][j][0] + bi0, d[mt][j][1] + bi1);
            float2 v1 = make_float2(d[mt][j][2] + bi0, d[mt][j][3] + bi1);
            *(float2*)&g_xg[m * G4 + n0g + col]       = v0;
            *(float2*)&g_xg[(m + 8) * G4 + n0g + col] = v1;
        }
    }
}

// ---------------------------------------------------------------------------
// Persistent recurrent kernel, bf16 mma, W_hh in registers.
// Barrier: per-CTA flag words (st.release / ld.acquire poll) — no shared-
// address atomics. h published via smem stage -> coalesced STG.128.
// ---------------------------------------------------------------------------
__global__ void __launch_bounds__(256, 1) lstm_seq_bf16(
    const float* __restrict__ w_hh, int store_hs)
{
    __shared__ uint4 Hsm[2][32][32];   // A-fragments of the 32-row h tile, 32KB
    __shared__ uint4 Hstage[2][32];    // outgoing h tile stage, 1KB

    int tid = threadIdx.x, lane = tid & 31, warp = tid >> 5;
    int wm = warp & 1, wn = warp >> 1;
    int g = lane >> 2, tig = lane & 3;
    int bt = blockIdx.x & 3, ct = blockIdx.x >> 2;
    int b0 = bt * 32, j0 = ct * 16;
    int odd = tig & 1;
    int rl  = wm * 16 + g + 8 * odd;
    int b   = b0 + rl;

    // ---- W_hh fragments into registers (held for all 1024 steps) ----
    unsigned wreg[2][32][2];
#pragma unroll
    for (int nt = 0; nt < 2; nt++) {
        int nl  = (wn * 2 + nt) * 8 + g;
        int row = (nl & 3) * Hz + j0 + (nl >> 2);
        const float* wr = &w_hh[(size_t)row * Hz];
#pragma unroll
        for (int ks = 0; ks < 32; ks++) {
#pragma unroll
            for (int r = 0; r < 2; r++) {
                float2 wv = *(const float2*)&wr[ks * 16 + 8 * r + 2 * tig];
                wreg[nt][ks][r] = pack_bf16x2(wv.x, wv.y);
            }
        }
    }

    float cst[2] = {0.0f, 0.0f};
    unsigned* flags = &g_flag[bt][0];
    uint4* buf0 = (uint4*)&g_phb[0][bt][0];
    uint4* buf1 = (uint4*)&g_phb[1][bt][0];

#pragma unroll 1
    for (int t = 0; t < Tz; t++) {
        // ---- prefetch xg (streaming; independent of h) ----
        float4 xv[2];
#pragma unroll
        for (int nt = 0; nt < 2; nt++) {
            int jjloc = (wn * 2 + nt) * 2 + (tig >> 1);
            xv[nt] = __ldcs((const float4*)
                &g_xg[((size_t)b * Tz + t) * G4 + ct * 64 + jjloc * 4]);
        }

        // ---- wait: all 32 CTAs of this group finished step t-1 ----
        if (warp == 0) {
            unsigned v;
            do {
                asm volatile("ld.acquire.gpu.global.u32 %0, [%1];"
                             : "=r"(v) : "l"(flags + lane) : "memory");
            } while (!__all_sync(0xffffffffu, (int)(v >= (unsigned)t)));
        }
        __syncthreads();

        // ---- copy h tile (frag layout): global -> smem ----
        {
            const uint4* src = (t & 1) ? buf1 : buf0;
            uint4* dstf = &Hsm[0][0][0];
#pragma unroll
            for (int i = 0; i < 8; i++) {
                int idx = i * 256 + tid;
                dstf[idx] = __ldcg(&src[idx]);
            }
        }
        __syncthreads();

        float d[2][4];
#pragma unroll
        for (int a = 0; a < 2; a++)
#pragma unroll
            for (int c = 0; c < 4; c++) d[a][c] = 0.0f;

#pragma unroll
        for (int ks = 0; ks < 32; ks++) {
            uint4 a = Hsm[wm][ks][lane];
            mma_bf16(d[0], a, wreg[0][ks][0], wreg[0][ks][1]);
            mma_bf16(d[1], a, wreg[1][ks][0], wreg[1][ks][1]);
        }

        // ---- epilogue: gate exchange, nonlinearity, stage h ----
#pragma unroll
        for (int nt = 0; nt < 2; nt++) {
            float p0 = __shfl_xor_sync(0xffffffffu, d[nt][0], 1);
            float p1 = __shfl_xor_sync(0xffffffffu, d[nt][1], 1);
            float p2 = __shfl_xor_sync(0xffffffffu, d[nt][2], 1);
            float p3 = __shfl_xor_sync(0xffffffffu, d[nt][3], 1);
            float gi, gf, gg, go;
            if (!odd) { gi = d[nt][0]; gf = d[nt][1]; gg = p0;       go = p1; }
            else      { gi = p2;       gf = p3;       gg = d[nt][2]; go = d[nt][3]; }

            gi += xv[nt].x; gf += xv[nt].y; gg += xv[nt].z; go += xv[nt].w;

            float i_ = siga(gi), f_ = siga(gf), g_ = tanha(gg), o_ = siga(go);
            float c = f_ * cst[nt] + i_ * g_;
            cst[nt] = c;
            float h = o_ * tanha(c);

            int jjloc = (wn * 2 + nt) * 2 + (tig >> 1);
            int kc = jjloc >> 3, tg2 = (jjloc & 7) >> 1, lo = jjloc & 1;
            __nv_bfloat16 hb = __float2bfloat16_rn(h);
            ((unsigned short*)&Hstage[wm][g * 4 + tg2])[(odd + 2 * kc) * 2 + lo] =
                *(unsigned short*)&hb;

            int jc = j0 + jjloc;
            if (store_hs)    g_hsb[((size_t)b * Tz + t) * Hz + jc] = hb;
            if (t == Tz - 1) g_hlast[b * Hz + jc] = h;
        }

        // ---- publish: coalesced STG.128, then release flag ----
        __syncthreads();
        if (tid < 64) {
            int w = tid >> 5, l = tid & 31;
            uint4* dst = (t & 1) ? buf0 : buf1;
            dst[(w * 32 + ct) * 32 + l] = Hstage[w][l];
        }
        __syncthreads();
        if (tid == 0) {
            asm volatile("st.release.gpu.global.u32 [%0], %1;"
                         :: "l"(flags + ct), "r"((unsigned)(t + 1)) : "memory");
        }
    }
}

// ---------------------------------------------------------------------------
__global__ void head_kernel(const float* __restrict__ fc_w,
                            const float* __restrict__ fc_b,
                            const float* __restrict__ fc2_w,
                            const float* __restrict__ fc2_b,
                            float* __restrict__ out)
{
    int b = blockIdx.x;
    int f = threadIdx.x;
    const float* hb = &g_hlast[b * Hz];
    float s = 0.0f;
    for (int k = 0; k < Hz; k += 4) {
        float4 hv = *(const float4*)&hb[k];
        float4 wv = *(const float4*)&fc_w[(size_t)f * Hz + k];
        s = fmaf(hv.x, wv.x, s);
        s = fmaf(hv.y, wv.y, s);
        s = fmaf(hv.z, wv.z, s);
        s = fmaf(hv.w, wv.w, s);
    }
    s += fc_b[f];
    s = fmaxf(s, 0.0f);
    float v = s * fc2_w[f];

    __shared__ float red[64];
    red[f] = v;
    __syncthreads();
    if (f == 0) {
        float z = 0.0f;
#pragma unroll
        for (int i = 0; i < 64; i++) z += red[i];
        z += fc2_b[0];
        out[b] = 1.0f / (1.0f + expf(-z));
    }
}

// ---------------------------------------------------------------------------
extern "C" void kernel_launch(void* const* d_in, const int* in_sizes, int n_in,
                              void* d_out, int out_size)
{
    const float* x      = (const float*)d_in[0];
    const float* w_ih0  = (const float*)d_in[2];
    const float* w_hh0  = (const float*)d_in[3];
    const float* b_ih0  = (const float*)d_in[4];
    const float* b_hh0  = (const float*)d_in[5];
    const float* w_ih1  = (const float*)d_in[6];
    const float* w_hh1  = (const float*)d_in[7];
    const float* b_ih1  = (const float*)d_in[8];
    const float* b_hh1  = (const float*)d_in[9];
    const float* fc_w   = (const float*)d_in[10];
    const float* fc_b   = (const float*)d_in[11];
    const float* fc2_w  = (const float*)d_in[12];
    const float* fc2_b  = (const float*)d_in[13];
    float* out = (float*)d_out;

    dim3 ggrid(G4 / 64, (Bz * Tz) / 128);   // (32, 1024)
    int nz = (2 * 4 * 8192 + 4 * 32 + 255) / 256;

    // Layer 0
    zero_state_kernel<<<nz, 256>>>();
    gemm_bf16_kernel<INz, false><<<ggrid, 256>>>(x, w_ih0, b_ih0, b_hh0);
    lstm_seq_bf16<<<NCTA, 256>>>(w_hh0, 1);

    // Layer 1
    zero_state_kernel<<<nz, 256>>>();
    gemm_bf16_kernel<Hz, true><<<ggrid, 256>>>(nullptr, w_ih1, b_ih1, b_hh1);
    lstm_seq_bf16<<<NCTA, 256>>>(w_hh1, 0);

    // FC head
    head_kernel<<<Bz, 64>>>(fc_w, fc_b, fc2_w, fc2_b, out);
}

// round 9
// speedup vs baseline: 1.0174x; 1.0174x over previous
#include <cuda_runtime.h>
#include <cuda_bf16.h>
#include <math.h>
#include <stdint.h>

#define Bz   128
#define Tz   1024
#define INz  256
#define Hz   512
#define G4   2048   // 4*H
#define NCTA 128

// ---------------- scratch (device globals) ---------------------------------
__device__ float g_xg[(size_t)Bz * Tz * G4];       // gate preacts, PERMUTED cols
__device__ __nv_bfloat16 g_hsb[(size_t)Bz * Tz * Hz]; // layer-0 hidden outputs, bf16 plain
__device__ unsigned g_phb[2][4][8192];             // h exchange, bf16 A-frag layout
__device__ float g_hlast[Bz * Hz];                 // final h of running layer
__device__ unsigned g_flag[4][32];                 // per-CTA progress flags (per bt group)

// ---------------------------------------------------------------------------
__device__ __forceinline__ void mma_bf16(float* d, const uint4& a, unsigned b0, unsigned b1) {
    asm volatile(
        "mma.sync.aligned.m16n8k16.row.col.f32.bf16.bf16.f32 "
        "{%0,%1,%2,%3}, {%4,%5,%6,%7}, {%8,%9}, {%0,%1,%2,%3};\n"
        : "+f"(d[0]), "+f"(d[1]), "+f"(d[2]), "+f"(d[3])
        : "r"(a.x), "r"(a.y), "r"(a.z), "r"(a.w), "r"(b0), "r"(b1));
}
__device__ __forceinline__ float tanha(float x) {
    float y; asm("tanh.approx.f32 %0, %1;" : "=f"(y) : "f"(x)); return y;
}
__device__ __forceinline__ float siga(float x) { return 0.5f * tanha(0.5f * x) + 0.5f; }
__device__ __forceinline__ unsigned pack_bf16x2(float x, float y) {
    __nv_bfloat162 v = __floats2bfloat162_rn(x, y);
    return *(unsigned*)&v;
}

// ---------------------------------------------------------------------------
__global__ void zero_state_kernel() {
    int i = blockIdx.x * blockDim.x + threadIdx.x;
    if (i < 2 * 4 * 8192) ((unsigned*)g_phb)[i] = 0u;
    else if (i < 2 * 4 * 8192 + 4 * 32) ((unsigned*)g_flag)[i - 2 * 4 * 8192] = 0u;
}

// ---------------------------------------------------------------------------
// Input GEMM, bf16 m16n8k16. BM=128, BN=64, BK=32, 256 thr (4m x 2n warps).
// Output to g_xg with permuted gate cols: n' = jj*4+gate, row = (n'&3)*Hz+(n'>>2)
// ---------------------------------------------------------------------------
template <int K, bool BF16IN>
__global__ void __launch_bounds__(256) gemm_bf16_kernel(
    const float* __restrict__ Xf, const float* __restrict__ W,
    const float* __restrict__ b1, const float* __restrict__ b2)
{
    __shared__ uint4 Abuf[8][2][32];   // [m16][k16 step][lane] 8KB
    __shared__ uint2 Bbuf[8][2][32];   // [n8][k16 step][lane]  2KB
    __shared__ float sbias[64];

    const __nv_bfloat16* __restrict__ Xb = g_hsb;

    int tid = threadIdx.x, lane = tid & 31, warp = tid >> 5;
    int wm = warp & 3, wn = warp >> 2;
    int g = lane >> 2, tig = lane & 3;
    size_t m0g = (size_t)blockIdx.y * 128;
    int    n0g = blockIdx.x * 64;

    if (tid < 64) {
        int ng  = n0g + tid;
        int row = (ng & 3) * Hz + (ng >> 2);
        sbias[tid] = b1[row] + b2[row];
    }

    float d[2][4][4];
#pragma unroll
    for (int a = 0; a < 2; a++)
#pragma unroll
        for (int b = 0; b < 4; b++)
#pragma unroll
            for (int c = 0; c < 4; c++) d[a][b][c] = 0.0f;

    for (int kb = 0; kb < K; kb += 32) {
        // ---- A fill: 4 quads/thread (quad = 4 consecutive k at one row) ----
#pragma unroll
        for (int i = 0; i < 4; i++) {
            int f4 = tid * 4 + i;            // 0..1023
            int m = f4 >> 3, q = f4 & 7;
            unsigned lo_, hi_;
            if (BF16IN) {
                uint2 u = *(const uint2*)&Xb[(m0g + m) * K + kb + q * 4];
                lo_ = u.x; hi_ = u.y;
            } else {
                float4 v = *(const float4*)&Xf[(m0g + m) * K + kb + q * 4];
                lo_ = pack_bf16x2(v.x, v.y); hi_ = pack_bf16x2(v.z, v.w);
            }
            int mt = m >> 4, gg = m & 7, odd = (m >> 3) & 1;
            int ks = q >> 2, kc = (q >> 1) & 1, tg2 = (q & 1) * 2;
            int e = odd + 2 * kc;
            ((unsigned*)&Abuf[mt][ks][gg * 4 + tg2])[e]     = lo_;
            ((unsigned*)&Abuf[mt][ks][gg * 4 + tg2 + 1])[e] = hi_;
        }
        // ---- B fill: 2 quads/thread ----
#pragma unroll
        for (int i = 0; i < 2; i++) {
            int fb = tid * 2 + i;            // 0..511
            int n = fb >> 3, q = fb & 7;
            int row = ((n0g + n) & 3) * Hz + ((n0g + n) >> 2);
            float4 v = *(const float4*)&W[(size_t)row * K + kb + q * 4];
            unsigned lo_ = pack_bf16x2(v.x, v.y), hi_ = pack_bf16x2(v.z, v.w);
            int nt = n >> 3, gb = n & 7;
            int ks = q >> 2, r = (q >> 1) & 1, tg = (q & 1) * 2;
            ((unsigned*)&Bbuf[nt][ks][gb * 4 + tg])[r]     = lo_;
            ((unsigned*)&Bbuf[nt][ks][gb * 4 + tg + 1])[r] = hi_;
        }
        __syncthreads();
#pragma unroll
        for (int ks = 0; ks < 2; ks++) {
            uint4 a0 = Abuf[wm * 2 + 0][ks][lane];
            uint4 a1 = Abuf[wm * 2 + 1][ks][lane];
#pragma unroll
            for (int j = 0; j < 4; j++) {
                uint2 bb = Bbuf[wn * 4 + j][ks][lane];
                mma_bf16(d[0][j], a0, bb.x, bb.y);
                mma_bf16(d[1][j], a1, bb.x, bb.y);
            }
        }
        __syncthreads();
    }

    // ---- epilogue: add bias, store permuted (fp32) ----
#pragma unroll
    for (int mt = 0; mt < 2; mt++) {
#pragma unroll
        for (int j = 0; j < 4; j++) {
            int col = wn * 32 + j * 8 + 2 * tig;
            float bi0 = sbias[col], bi1 = sbias[col + 1];
            size_t m = m0g + wm * 32 + mt * 16 + g;
            float2 v0 = make_float2(d[mt][j][0] + bi0, d[mt][j][1] + bi1);
            float2 v1 = make_float2(d[mt][j][2] + bi0, d[mt][j][3] + bi1);
            *(float2*)&g_xg[m * G4 + n0g + col]       = v0;
            *(float2*)&g_xg[(m + 8) * G4 + n0g + col] = v1;
        }
    }
}

// ---------------------------------------------------------------------------
// Persistent recurrent kernel, bf16 mma, W_hh in registers.
// Barrier: per-CTA flag words (st.release / ld.acquire poll) — no shared-
// address atomics. h published via smem stage -> coalesced STG.128.
// ---------------------------------------------------------------------------
__global__ void __launch_bounds__(256, 1) lstm_seq_bf16(
    const float* __restrict__ w_hh, int store_hs)
{
    __shared__ uint4 Hsm[2][32][32];   // A-fragments of the 32-row h tile, 32KB
    __shared__ uint4 Hstage[2][32];    // outgoing h tile stage, 1KB

    int tid = threadIdx.x, lane = tid & 31, warp = tid >> 5;
    int wm = warp & 1, wn = warp >> 1;
    int g = lane >> 2, tig = lane & 3;
    int bt = blockIdx.x & 3, ct = blockIdx.x >> 2;
    int b0 = bt * 32, j0 = ct * 16;
    int odd = tig & 1;
    int rl  = wm * 16 + g + 8 * odd;
    int b   = b0 + rl;

    // ---- W_hh fragments into registers (held for all 1024 steps) ----
    unsigned wreg[2][32][2];
#pragma unroll
    for (int nt = 0; nt < 2; nt++) {
        int nl  = (wn * 2 + nt) * 8 + g;
        int row = (nl & 3) * Hz + j0 + (nl >> 2);
        const float* wr = &w_hh[(size_t)row * Hz];
#pragma unroll
        for (int ks = 0; ks < 32; ks++) {
#pragma unroll
            for (int r = 0; r < 2; r++) {
                float2 wv = *(const float2*)&wr[ks * 16 + 8 * r + 2 * tig];
                wreg[nt][ks][r] = pack_bf16x2(wv.x, wv.y);
            }
        }
    }

    float cst[2] = {0.0f, 0.0f};
    unsigned* flags = &g_flag[bt][0];
    uint4* buf0 = (uint4*)&g_phb[0][bt][0];
    uint4* buf1 = (uint4*)&g_phb[1][bt][0];

#pragma unroll 1
    for (int t = 0; t < Tz; t++) {
        // ---- prefetch xg (streaming; independent of h) ----
        float4 xv[2];
#pragma unroll
        for (int nt = 0; nt < 2; nt++) {
            int jjloc = (wn * 2 + nt) * 2 + (tig >> 1);
            xv[nt] = __ldcs((const float4*)
                &g_xg[((size_t)b * Tz + t) * G4 + ct * 64 + jjloc * 4]);
        }

        // ---- wait: all 32 CTAs of this group finished step t-1 ----
        if (warp == 0) {
            unsigned v;
            do {
                asm volatile("ld.acquire.gpu.global.u32 %0, [%1];"
                             : "=r"(v) : "l"(flags + lane) : "memory");
            } while (!__all_sync(0xffffffffu, (int)(v >= (unsigned)t)));
        }
        __syncthreads();

        // ---- copy h tile (frag layout): global -> smem ----
        {
            const uint4* src = (t & 1) ? buf1 : buf0;
            uint4* dstf = &Hsm[0][0][0];
#pragma unroll
            for (int i = 0; i < 8; i++) {
                int idx = i * 256 + tid;
                dstf[idx] = __ldcg(&src[idx]);
            }
        }
        __syncthreads();

        float d[2][4];
#pragma unroll
        for (int a = 0; a < 2; a++)
#pragma unroll
            for (int c = 0; c < 4; c++) d[a][c] = 0.0f;

#pragma unroll
        for (int ks = 0; ks < 32; ks++) {
            uint4 a = Hsm[wm][ks][lane];
            mma_bf16(d[0], a, wreg[0][ks][0], wreg[0][ks][1]);
            mma_bf16(d[1], a, wreg[1][ks][0], wreg[1][ks][1]);
        }

        // ---- epilogue: gate exchange, nonlinearity, stage h ----
#pragma unroll
        for (int nt = 0; nt < 2; nt++) {
            float p0 = __shfl_xor_sync(0xffffffffu, d[nt][0], 1);
            float p1 = __shfl_xor_sync(0xffffffffu, d[nt][1], 1);
            float p2 = __shfl_xor_sync(0xffffffffu, d[nt][2], 1);
            float p3 = __shfl_xor_sync(0xffffffffu, d[nt][3], 1);
            float gi, gf, gg, go;
            if (!odd) { gi = d[nt][0]; gf = d[nt][1]; gg = p0;       go = p1; }
            else      { gi = p2;       gf = p3;       gg = d[nt][2]; go = d[nt][3]; }

            gi += xv[nt].x; gf += xv[nt].y; gg += xv[nt].z; go += xv[nt].w;

            float i_ = siga(gi), f_ = siga(gf), g_ = tanha(gg), o_ = siga(go);
            float c = f_ * cst[nt] + i_ * g_;
            cst[nt] = c;
            float h = o_ * tanha(c);

            int jjloc = (wn * 2 + nt) * 2 + (tig >> 1);
            int kc = jjloc >> 3, tg2 = (jjloc & 7) >> 1, lo = jjloc & 1;
            __nv_bfloat16 hb = __float2bfloat16_rn(h);
            ((unsigned short*)&Hstage[wm][g * 4 + tg2])[(odd + 2 * kc) * 2 + lo] =
                *(unsigned short*)&hb;

            int jc = j0 + jjloc;
            if (store_hs)    g_hsb[((size_t)b * Tz + t) * Hz + jc] = hb;
            if (t == Tz - 1) g_hlast[b * Hz + jc] = h;
        }

        // ---- publish: coalesced STG.128, then release flag ----
        __syncthreads();
        if (tid < 64) {
            int w = tid >> 5, l = tid & 31;
            uint4* dst = (t & 1) ? buf0 : buf1;
            dst[(w * 32 + ct) * 32 + l] = Hstage[w][l];
        }
        __syncthreads();
        if (tid == 0) {
            asm volatile("st.release.gpu.global.u32 [%0], %1;"
                         :: "l"(flags + ct), "r"((unsigned)(t + 1)) : "memory");
        }
    }
}

// ---------------------------------------------------------------------------
__global__ void head_kernel(const float* __restrict__ fc_w,
                            const float* __restrict__ fc_b,
                            const float* __restrict__ fc2_w,
                            const float* __restrict__ fc2_b,
                            float* __restrict__ out)
{
    int b = blockIdx.x;
    int f = threadIdx.x;
    const float* hb = &g_hlast[b * Hz];
    float s = 0.0f;
    for (int k = 0; k < Hz; k += 4) {
        float4 hv = *(const float4*)&hb[k];
        float4 wv = *(const float4*)&fc_w[(size_t)f * Hz + k];
        s = fmaf(hv.x, wv.x, s);
        s = fmaf(hv.y, wv.y, s);
        s = fmaf(hv.z, wv.z, s);
        s = fmaf(hv.w, wv.w, s);
    }
    s += fc_b[f];
    s = fmaxf(s, 0.0f);
    float v = s * fc2_w[f];

    __shared__ float red[64];
    red[f] = v;
    __syncthreads();
    if (f == 0) {
        float z = 0.0f;
#pragma unroll
        for (int i = 0; i < 64; i++) z += red[i];
        z += fc2_b[0];
        out[b] = 1.0f / (1.0f + expf(-z));
    }
}

// ---------------------------------------------------------------------------
extern "C" void kernel_launch(void* const* d_in, const int* in_sizes, int n_in,
                              void* d_out, int out_size)
{
    const float* x      = (const float*)d_in[0];
    const float* w_ih0  = (const float*)d_in[2];
    const float* w_hh0  = (const float*)d_in[3];
    const float* b_ih0  = (const float*)d_in[4];
    const float* b_hh0  = (const float*)d_in[5];
    const float* w_ih1  = (const float*)d_in[6];
    const float* w_hh1  = (const float*)d_in[7];
    const float* b_ih1  = (const float*)d_in[8];
    const float* b_hh1  = (const float*)d_in[9];
    const float* fc_w   = (const float*)d_in[10];
    const float* fc_b   = (const float*)d_in[11];
    const float* fc2_w  = (const float*)d_in[12];
    const float* fc2_b  = (const float*)d_in[13];
    float* out = (float*)d_out;

    dim3 ggrid(G4 / 64, (Bz * Tz) / 128);   // (32, 1024)
    int nz = (2 * 4 * 8192 + 4 * 32 + 255) / 256;

    // Layer 0
    zero_state_kernel<<<nz, 256>>>();
    gemm_bf16_kernel<INz, false><<<ggrid, 256>>>(x, w_ih0, b_ih0, b_hh0);
    lstm_seq_bf16<<<NCTA, 256>>>(w_hh0, 1);

    // Layer 1
    zero_state_kernel<<<nz, 256>>>();
    gemm_bf16_kernel<Hz, true><<<ggrid, 256>>>(nullptr, w_ih1, b_ih1, b_hh1);
    lstm_seq_bf16<<<NCTA, 256>>>(w_hh1, 0);

    // FC head
    head_kernel<<<Bz, 64>>>(fc_w, fc_b, fc2_w, fc2_b, out);
}